// round 3
// baseline (speedup 1.0000x reference)
#include <cuda_runtime.h>

#define DINL __device__ __forceinline__

constexpr int N_NODES = 50000;
constexpr int N_EDGES = 1600000;
constexpr int NL = 5;
constexpr int NG = 4;
constexpr float EPS = 1e-5f;

__device__ float g_h  [N_NODES * 64];
__device__ float g_hd [N_NODES * 64];
__device__ float g_hs [N_NODES * 64];
__device__ float g_agg[N_NODES * 64];
__device__ float g_pool[NG * 64];

typedef unsigned long long u64;

DINL u64 pk2(float x, float y) { u64 r; asm("mov.b64 %0,{%1,%2};" : "=l"(r) : "f"(x), "f"(y)); return r; }
DINL u64 dup2(float x) { return pk2(x, x); }
DINL float2 upk(u64 v) { float2 r; asm("mov.b64 {%0,%1},%2;" : "=f"(r.x), "=f"(r.y) : "l"(v)); return r; }
DINL u64 f2u(float2 v) { return pk2(v.x, v.y); }
DINL u64 ffma2(u64 a, u64 b, u64 c) {
    u64 d; asm("fma.rn.f32x2 %0,%1,%2,%3;" : "=l"(d) : "l"(a), "l"(b), "l"(c)); return d;
}
DINL u64 add2(u64 a, u64 b) {
    u64 d; asm("add.rn.f32x2 %0,%1,%2;" : "=l"(d) : "l"(a), "l"(b)); return d;
}
DINL void red2(float* p, float x, float y) {
    asm volatile("red.global.add.v2.f32 [%0], {%1,%2};" :: "l"(p), "f"(x), "f"(y) : "memory");
}
DINL float silu(float x) { return __fdividef(x, 1.f + __expf(-x)); }

// ============================ encoder ============================
__global__ void __launch_bounds__(256) k_encoder(
    const float* __restrict__ x, const int* __restrict__ batch,
    const float* __restrict__ casep, const float* __restrict__ bcp,
    const float* __restrict__ W1, const float* __restrict__ b1,
    const float* __restrict__ W2, const float* __restrict__ b2,
    const float* __restrict__ gam, const float* __restrict__ bet)
{
    __shared__ float sW1[16 * 64], sW2[64 * 64], sb1[64], sb2[64], sg[64], sbe[64];
    __shared__ float sH[8][64];
    int tid = threadIdx.x;
    for (int i = tid; i < 16 * 64; i += 256) sW1[i] = W1[i];
    for (int i = tid; i < 64 * 64; i += 256) sW2[i] = W2[i];
    if (tid < 64) { sb1[tid] = b1[tid]; sb2[tid] = b2[tid]; sg[tid] = gam[tid]; sbe[tid] = bet[tid]; }
    __syncthreads();
    int w = tid >> 5, ld = tid & 31, c0 = 2 * ld;
    int n = blockIdx.x * 8 + w;
    if (n >= N_NODES) return;
    float in[16];
#pragma unroll
    for (int k = 0; k < 8; k++) in[k] = __ldg(&x[n * 8 + k]);
    int g = __ldg(&batch[n]);
#pragma unroll
    for (int k = 0; k < 4; k++) { in[8 + k] = __ldg(&casep[g * 4 + k]); in[12 + k] = __ldg(&bcp[g * 4 + k]); }
    const u64* W1u = (const u64*)sW1;
    u64 acc = ((const u64*)sb1)[ld];
#pragma unroll
    for (int k = 0; k < 16; k++) acc = ffma2(dup2(in[k]), W1u[k * 32 + ld], acc);
    float2 a = upk(acc);
    a.x = silu(a.x); a.y = silu(a.y);
    sH[w][c0] = a.x; sH[w][c0 + 1] = a.y;
    __syncwarp();
    const u64* W2u = (const u64*)sW2;
    u64 acc2 = ((const u64*)sb2)[ld];
#pragma unroll 8
    for (int k = 0; k < 64; k++) acc2 = ffma2(dup2(sH[w][k]), W2u[k * 32 + ld], acc2);
    float2 v = upk(acc2);
    float s = v.x + v.y, q = v.x * v.x + v.y * v.y;
#pragma unroll
    for (int o = 16; o; o >>= 1) { s += __shfl_xor_sync(~0u, s, o); q += __shfl_xor_sync(~0u, q, o); }
    float m = s * (1.f / 64.f), var = q * (1.f / 64.f) - m * m, rs = rsqrtf(var + EPS);
    float2 out;
    out.x = (v.x - m) * rs * sg[c0] + sbe[c0];
    out.y = (v.y - m) * rs * sg[c0 + 1] + sbe[c0 + 1];
    *(float2*)(g_h + (size_t)n * 64 + c0) = out;
}

// ============================ node pre: Hd/Hs, 8 nodes/warp ============================
__global__ void __launch_bounds__(256) k_node_pre(const float* __restrict__ eW1l)
{
    extern __shared__ float ps[];
    float* sWA = ps;
    float* sWB = ps + 4096;
    float* sInAll = ps + 8192;
    int tid = threadIdx.x;
    for (int i = tid; i < 4096; i += 256) { sWA[i] = eW1l[i]; sWB[i] = eW1l[4096 + i]; }
    __syncthreads();
    int w = tid >> 5, ld = tid & 31;
    int nb = ld >> 3, cb = ld & 7;
    float* sIn = sInAll + w * (8 * 68);
    const ulonglong2* WAu = (const ulonglong2*)sWA;   // row k: 16 ull2
    const ulonglong2* WBu = (const ulonglong2*)sWB;
    int gw = (blockIdx.x * 256 + tid) >> 5;
    int nw = (gridDim.x * 256) >> 5;
    for (int grp = gw; grp < N_NODES / 8; grp += nw) {
        int n0 = grp * 8;
        __syncwarp();
#pragma unroll
        for (int r = 0; r < 4; r++) {
            int t = r * 32 + ld;
            int n = t >> 4, c4 = (t & 15) * 4;
            float4 v = *(const float4*)(g_h + (size_t)(n0 + n) * 64 + c4);
            *(float4*)&sIn[n * 68 + c4] = v;
        }
        __syncwarp();
        u64 aA[2][4], aB[2][4];
#pragma unroll
        for (int i = 0; i < 2; i++)
#pragma unroll
            for (int j = 0; j < 4; j++) { aA[i][j] = 0ull; aB[i][j] = 0ull; }
#pragma unroll 4
        for (int k = 0; k < 64; k++) {
            u64 d0 = dup2(sIn[(nb * 2 + 0) * 68 + k]);
            u64 d1 = dup2(sIn[(nb * 2 + 1) * 68 + k]);
            ulonglong2 A0 = WAu[k * 16 + cb * 2], A1 = WAu[k * 16 + cb * 2 + 1];
            ulonglong2 B0 = WBu[k * 16 + cb * 2], B1 = WBu[k * 16 + cb * 2 + 1];
            aA[0][0] = ffma2(d0, A0.x, aA[0][0]); aA[0][1] = ffma2(d0, A0.y, aA[0][1]);
            aA[0][2] = ffma2(d0, A1.x, aA[0][2]); aA[0][3] = ffma2(d0, A1.y, aA[0][3]);
            aA[1][0] = ffma2(d1, A0.x, aA[1][0]); aA[1][1] = ffma2(d1, A0.y, aA[1][1]);
            aA[1][2] = ffma2(d1, A1.x, aA[1][2]); aA[1][3] = ffma2(d1, A1.y, aA[1][3]);
            aB[0][0] = ffma2(d0, B0.x, aB[0][0]); aB[0][1] = ffma2(d0, B0.y, aB[0][1]);
            aB[0][2] = ffma2(d0, B1.x, aB[0][2]); aB[0][3] = ffma2(d0, B1.y, aB[0][3]);
            aB[1][0] = ffma2(d1, B0.x, aB[1][0]); aB[1][1] = ffma2(d1, B0.y, aB[1][1]);
            aB[1][2] = ffma2(d1, B1.x, aB[1][2]); aB[1][3] = ffma2(d1, B1.y, aB[1][3]);
        }
#pragma unroll
        for (int i = 0; i < 2; i++) {
            int n = n0 + nb * 2 + i;
            ulonglong2 t;
            t.x = aA[i][0]; t.y = aA[i][1];
            *(ulonglong2*)(g_hd + (size_t)n * 64 + cb * 8) = t;
            t.x = aA[i][2]; t.y = aA[i][3];
            *(ulonglong2*)(g_hd + (size_t)n * 64 + cb * 8 + 4) = t;
            t.x = aB[i][0]; t.y = aB[i][1];
            *(ulonglong2*)(g_hs + (size_t)n * 64 + cb * 8) = t;
            t.x = aB[i][2]; t.y = aB[i][3];
            *(ulonglong2*)(g_hs + (size_t)n * 64 + cb * 8 + 4) = t;
            *(float4*)(g_agg + (size_t)n * 64 + cb * 8)     = make_float4(0.f, 0.f, 0.f, 0.f);
            *(float4*)(g_agg + (size_t)n * 64 + cb * 8 + 4) = make_float4(0.f, 0.f, 0.f, 0.f);
        }
    }
}

// ============================ edge kernel: 16 edges/warp ============================
// dyn smem: sW2[4096] sW1c[320] sb1 sb2 sg sbe [64 ea] | per-warp sM[64*20]
__global__ void __launch_bounds__(256) k_edge(
    const int* __restrict__ ei, const float* __restrict__ eattr,
    const float* __restrict__ W1c, const float* __restrict__ b1,
    const float* __restrict__ W2, const float* __restrict__ b2,
    const float* __restrict__ gam, const float* __restrict__ bet)
{
    extern __shared__ float es[];
    float* sW2  = es;
    float* sW1c = es + 4096;
    float* sb1  = es + 4416;
    float* sb2  = es + 4480;
    float* sg   = es + 4544;
    float* sbe  = es + 4608;
    float* sMall = es + 4672;
    int tid = threadIdx.x;
    for (int i = tid; i < 4096; i += 256) sW2[i] = W2[i];
    for (int i = tid; i < 320; i += 256) sW1c[i] = W1c[i];
    if (tid < 64) { sb1[tid] = b1[tid]; sb2[tid] = b2[tid]; sg[tid] = gam[tid]; sbe[tid] = bet[tid]; }
    __syncthreads();
    int w = tid >> 5, ld = tid & 31;
    int pe = ld >> 1, half = ld & 1;
    int eb = ld >> 3, cb = ld & 7;
    float* sM = sMall + w * 1280;
    const ulonglong2* W2u  = (const ulonglong2*)sW2;    // row k: 16 ull2
    const ulonglong2* W1cu = (const ulonglong2*)sW1c;   // row r: 16 ull2
    const ulonglong2* b1u  = (const ulonglong2*)sb1;    // 16 ull2
    const u64* b2u = (const u64*)sb2;
    const float4* gv4  = (const float4*)sg;
    const float4* bev4 = (const float4*)sbe;
    int gw = (blockIdx.x * 256 + tid) >> 5;
    int nw = (gridDim.x * 256) >> 5;
    for (int grp = gw; grp < N_EDGES / 16; grp += nw) {
        int e = grp * 16 + pe;
        int sidx = __ldg(&ei[e]);
        int didx = __ldg(&ei[N_EDGES + e]);
        u64 ead[5];
#pragma unroll
        for (int r = 0; r < 5; r++) ead[r] = dup2(__ldg(&eattr[(size_t)e * 5 + r]));
        const ulonglong2* hdp = (const ulonglong2*)(g_hd + (size_t)didx * 64 + half * 32);
        const ulonglong2* hsp = (const ulonglong2*)(g_hs + (size_t)sidx * 64 + half * 32);
        u64 acc1[16];
#pragma unroll
        for (int j = 0; j < 8; j++) {
            ulonglong2 hdj = hdp[j];
            ulonglong2 hsj = hsp[j];
            ulonglong2 bj  = b1u[half * 8 + j];
            u64 a0 = add2(add2(hdj.x, hsj.x), bj.x);
            u64 a1 = add2(add2(hdj.y, hsj.y), bj.y);
#pragma unroll
            for (int r = 0; r < 5; r++) {
                ulonglong2 wv = W1cu[r * 16 + half * 8 + j];
                a0 = ffma2(ead[r], wv.x, a0);
                a1 = ffma2(ead[r], wv.y, a1);
            }
            acc1[2 * j] = a0; acc1[2 * j + 1] = a1;
        }
        __syncwarp();   // WAR vs previous iteration's sM reads
#pragma unroll
        for (int p = 0; p < 16; p++) {
            float2 v = upk(acc1[p]);
            v.x = silu(v.x); v.y = silu(v.y);
            int k0 = half * 32 + 2 * p;
            sM[k0 * 20 + pe]       = v.x;
            sM[(k0 + 1) * 20 + pe] = v.y;
        }
        __syncwarp();
        // k-loop: 16 edges x 64 cols, thread = 4 edges x 8 cols
        u64 acc[4][4];
#pragma unroll
        for (int i = 0; i < 4; i++)
#pragma unroll
            for (int j = 0; j < 4; j++) acc[i][j] = b2u[cb * 4 + j];
#pragma unroll 4
        for (int k = 0; k < 64; k++) {
            float4 mv = *(const float4*)&sM[k * 20 + eb * 4];
            ulonglong2 w0 = W2u[k * 16 + cb * 2];
            ulonglong2 w1 = W2u[k * 16 + cb * 2 + 1];
            u64 m0 = dup2(mv.x), m1 = dup2(mv.y), m2 = dup2(mv.z), m3 = dup2(mv.w);
            acc[0][0] = ffma2(m0, w0.x, acc[0][0]); acc[0][1] = ffma2(m0, w0.y, acc[0][1]);
            acc[0][2] = ffma2(m0, w1.x, acc[0][2]); acc[0][3] = ffma2(m0, w1.y, acc[0][3]);
            acc[1][0] = ffma2(m1, w0.x, acc[1][0]); acc[1][1] = ffma2(m1, w0.y, acc[1][1]);
            acc[1][2] = ffma2(m1, w1.x, acc[1][2]); acc[1][3] = ffma2(m1, w1.y, acc[1][3]);
            acc[2][0] = ffma2(m2, w0.x, acc[2][0]); acc[2][1] = ffma2(m2, w0.y, acc[2][1]);
            acc[2][2] = ffma2(m2, w1.x, acc[2][2]); acc[2][3] = ffma2(m2, w1.y, acc[2][3]);
            acc[3][0] = ffma2(m3, w0.x, acc[3][0]); acc[3][1] = ffma2(m3, w0.y, acc[3][1]);
            acc[3][2] = ffma2(m3, w1.x, acc[3][2]); acc[3][3] = ffma2(m3, w1.y, acc[3][3]);
        }
        // LN per edge + scatter
        float s[4], qq[4];
#pragma unroll
        for (int i = 0; i < 4; i++) {
            float2 v0 = upk(acc[i][0]), v1 = upk(acc[i][1]), v2 = upk(acc[i][2]), v3 = upk(acc[i][3]);
            s[i] = v0.x + v0.y + v1.x + v1.y + v2.x + v2.y + v3.x + v3.y;
            qq[i] = v0.x * v0.x + v0.y * v0.y + v1.x * v1.x + v1.y * v1.y
                  + v2.x * v2.x + v2.y * v2.y + v3.x * v3.x + v3.y * v3.y;
        }
#pragma unroll
        for (int o = 4; o; o >>= 1) {
#pragma unroll
            for (int i = 0; i < 4; i++) {
                s[i] += __shfl_xor_sync(~0u, s[i], o);
                qq[i] += __shfl_xor_sync(~0u, qq[i], o);
            }
        }
        float4 gA = gv4[cb * 2], gB = gv4[cb * 2 + 1];
        float4 beA = bev4[cb * 2], beB = bev4[cb * 2 + 1];
#pragma unroll
        for (int i = 0; i < 4; i++) {
            int dI = __shfl_sync(~0u, didx, (eb * 4 + i) * 2);
            float mn = s[i] * (1.f / 64.f);
            float rs = rsqrtf(qq[i] * (1.f / 64.f) - mn * mn + EPS);
            float2 v0 = upk(acc[i][0]), v1 = upk(acc[i][1]), v2 = upk(acc[i][2]), v3 = upk(acc[i][3]);
            float* base = g_agg + (size_t)dI * 64 + cb * 8;
            red2(base + 0, (v0.x - mn) * rs * gA.x + beA.x, (v0.y - mn) * rs * gA.y + beA.y);
            red2(base + 2, (v1.x - mn) * rs * gA.z + beA.z, (v1.y - mn) * rs * gA.w + beA.w);
            red2(base + 4, (v2.x - mn) * rs * gB.x + beB.x, (v2.y - mn) * rs * gB.y + beB.y);
            red2(base + 6, (v3.x - mn) * rs * gB.z + beB.z, (v3.y - mn) * rs * gB.w + beB.w);
        }
    }
}

// ============================ node update: 4 nodes/warp ============================
// dyn smem: sW1[8192] sW2[4096] biases [256] | per-warp sIn[4*132] sMid[4*68]
__global__ void __launch_bounds__(256) k_node_upd(
    const float* __restrict__ W1, const float* __restrict__ b1,
    const float* __restrict__ W2, const float* __restrict__ b2,
    const float* __restrict__ gam, const float* __restrict__ bet)
{
    extern __shared__ float us[];
    float* sW1 = us;
    float* sW2 = us + 8192;
    float* sb1 = us + 12288;
    float* sb2 = us + 12352;
    float* sg  = us + 12416;
    float* sbe = us + 12480;
    float* sPer = us + 12544;
    int tid = threadIdx.x;
    for (int i = tid; i < 8192; i += 256) sW1[i] = W1[i];
    for (int i = tid; i < 4096; i += 256) sW2[i] = W2[i];
    if (tid < 64) { sb1[tid] = b1[tid]; sb2[tid] = b2[tid]; sg[tid] = gam[tid]; sbe[tid] = bet[tid]; }
    __syncthreads();
    int w = tid >> 5, ld = tid & 31;
    int nb = ld >> 3, cb = ld & 7;
    float* sIn  = sPer + w * (4 * 132 + 4 * 68);
    float* sMid = sIn + 4 * 132;
    const ulonglong2* W1u = (const ulonglong2*)sW1;
    const ulonglong2* W2u = (const ulonglong2*)sW2;
    const u64* b1u = (const u64*)sb1;
    const u64* b2u = (const u64*)sb2;
    const float4* gv4  = (const float4*)sg;
    const float4* bev4 = (const float4*)sbe;
    int gw = (blockIdx.x * 256 + tid) >> 5;
    int nw = (gridDim.x * 256) >> 5;
    for (int grp = gw; grp < N_NODES / 4; grp += nw) {
        int n0 = grp * 4;
        __syncwarp();
#pragma unroll
        for (int r = 0; r < 4; r++) {
            int c4 = ld * 4;
            float4 v;
            if (c4 < 64) v = *(const float4*)(g_h + (size_t)(n0 + r) * 64 + c4);
            else         v = *(const float4*)(g_agg + (size_t)(n0 + r) * 64 + (c4 - 64));
            *(float4*)&sIn[r * 132 + c4] = v;
        }
        __syncwarp();
        // GEMM1: [4 x 128] @ [128 x 64], thread = 1 node x 8 cols
        u64 a1[4];
#pragma unroll
        for (int j = 0; j < 4; j++) a1[j] = b1u[cb * 4 + j];
#pragma unroll 4
        for (int k = 0; k < 128; k++) {
            u64 d0 = dup2(sIn[nb * 132 + k]);
            ulonglong2 w0 = W1u[k * 16 + cb * 2], w1 = W1u[k * 16 + cb * 2 + 1];
            a1[0] = ffma2(d0, w0.x, a1[0]); a1[1] = ffma2(d0, w0.y, a1[1]);
            a1[2] = ffma2(d0, w1.x, a1[2]); a1[3] = ffma2(d0, w1.y, a1[3]);
        }
#pragma unroll
        for (int j = 0; j < 4; j++) {
            float2 v = upk(a1[j]);
            v.x = silu(v.x); v.y = silu(v.y);
            *(float2*)&sMid[nb * 68 + cb * 8 + 2 * j] = v;
        }
        __syncwarp();
        // GEMM2: [4 x 64] @ [64 x 64]
        u64 a2[4];
#pragma unroll
        for (int j = 0; j < 4; j++) a2[j] = b2u[cb * 4 + j];
#pragma unroll 4
        for (int k = 0; k < 64; k++) {
            u64 d0 = dup2(sMid[nb * 68 + k]);
            ulonglong2 w0 = W2u[k * 16 + cb * 2], w1 = W2u[k * 16 + cb * 2 + 1];
            a2[0] = ffma2(d0, w0.x, a2[0]); a2[1] = ffma2(d0, w0.y, a2[1]);
            a2[2] = ffma2(d0, w1.x, a2[2]); a2[3] = ffma2(d0, w1.y, a2[3]);
        }
        // LN + residual
        float2 v0 = upk(a2[0]), v1 = upk(a2[1]), v2 = upk(a2[2]), v3 = upk(a2[3]);
        float s = v0.x + v0.y + v1.x + v1.y + v2.x + v2.y + v3.x + v3.y;
        float q = v0.x * v0.x + v0.y * v0.y + v1.x * v1.x + v1.y * v1.y
                + v2.x * v2.x + v2.y * v2.y + v3.x * v3.x + v3.y * v3.y;
#pragma unroll
        for (int o = 4; o; o >>= 1) { s += __shfl_xor_sync(~0u, s, o); q += __shfl_xor_sync(~0u, q, o); }
        float mn = s * (1.f / 64.f);
        float rs = rsqrtf(q * (1.f / 64.f) - mn * mn + EPS);
        float4 gA = gv4[cb * 2], gB = gv4[cb * 2 + 1];
        float4 beA = bev4[cb * 2], beB = bev4[cb * 2 + 1];
        float4 h0 = *(const float4*)&sIn[nb * 132 + cb * 8];
        float4 h1 = *(const float4*)&sIn[nb * 132 + cb * 8 + 4];
        float4 o0, o1;
        o0.x = h0.x + (v0.x - mn) * rs * gA.x + beA.x;
        o0.y = h0.y + (v0.y - mn) * rs * gA.y + beA.y;
        o0.z = h0.z + (v1.x - mn) * rs * gA.z + beA.z;
        o0.w = h0.w + (v1.y - mn) * rs * gA.w + beA.w;
        o1.x = h1.x + (v2.x - mn) * rs * gB.x + beB.x;
        o1.y = h1.y + (v2.y - mn) * rs * gB.y + beB.y;
        o1.z = h1.z + (v3.x - mn) * rs * gB.z + beB.z;
        o1.w = h1.w + (v3.y - mn) * rs * gB.w + beB.w;
        *(float4*)(g_h + (size_t)(n0 + nb) * 64 + cb * 8)     = o0;
        *(float4*)(g_h + (size_t)(n0 + nb) * 64 + cb * 8 + 4) = o1;
    }
}

__global__ void k_zero_pool() { int t = threadIdx.x; if (t < NG * 64) g_pool[t] = 0.f; }

// ============================ local decoder + pooling ============================
__global__ void __launch_bounds__(256) k_decoder_local(
    const float* __restrict__ W1, const float* __restrict__ b1,
    const float* __restrict__ W2, const float* __restrict__ b2,
    const int* __restrict__ batch, float* __restrict__ out)
{
    __shared__ float sW1[4096], sW2[64 * 6], sb1[64], sb2_[8];
    __shared__ float sH[8][64], sU[8][64];
    int tid = threadIdx.x;
    for (int i = tid; i < 4096; i += 256) sW1[i] = W1[i];
    for (int i = tid; i < 384; i += 256) sW2[i] = W2[i];
    if (tid < 64) sb1[tid] = b1[tid];
    if (tid < 6) sb2_[tid] = b2[tid];
    __syncthreads();
    int w = tid >> 5, ld = tid & 31, c0 = 2 * ld;
    int n = blockIdx.x * 8 + w;
    if (n >= N_NODES) return;
    float2 hv = *(const float2*)(g_h + (size_t)n * 64 + c0);
    sH[w][c0] = hv.x; sH[w][c0 + 1] = hv.y;
    __syncwarp();
    const u64* W1u = (const u64*)sW1;
    u64 acc = ((const u64*)sb1)[ld];
#pragma unroll 8
    for (int k = 0; k < 64; k++) acc = ffma2(dup2(sH[w][k]), W1u[k * 32 + ld], acc);
    float2 u = upk(acc); u.x = silu(u.x); u.y = silu(u.y);
    sU[w][c0] = u.x; sU[w][c0 + 1] = u.y;
    __syncwarp();
    if (ld < 6) {
        float o = sb2_[ld];
#pragma unroll
        for (int k = 0; k < 64; k++) o += sU[w][k] * sW2[k * 6 + ld];
        out[(size_t)n * 6 + ld] = o;
    }
    int g = __ldg(&batch[n]);
    red2(g_pool + g * 64 + c0, hv.x, hv.y);
}

// ============================ global decoder ============================
__global__ void k_global(const int* __restrict__ batch,
    const float* __restrict__ W1, const float* __restrict__ b1,
    const float* __restrict__ W2, const float* __restrict__ b2,
    float* __restrict__ out)
{
    __shared__ float sp[NG * 64];
    __shared__ float su[NG * 32];
    __shared__ int bnd[NG + 1];
    int t = threadIdx.x; // 128 threads
    if (t <= NG) {
        int lo = 0, hi = N_NODES;
        while (lo < hi) { int mid = (lo + hi) >> 1; if (batch[mid] < t) lo = mid + 1; else hi = mid; }
        bnd[t] = lo;
    }
    __syncthreads();
    for (int i = t; i < NG * 64; i += 128) {
        int g = i >> 6;
        float cnt = (float)(bnd[g + 1] - bnd[g]);
        sp[i] = g_pool[i] / fmaxf(cnt, 1.f);
    }
    __syncthreads();
    {
        int g = t >> 5, j = t & 31;
        float a = b1[j];
#pragma unroll
        for (int k = 0; k < 64; k++) a += sp[g * 64 + k] * W1[k * 32 + j];
        su[g * 32 + j] = silu(a);
    }
    __syncthreads();
    if (t < NG * 4) {
        int g = t >> 2, j = t & 3;
        float o = b2[j];
#pragma unroll
        for (int k = 0; k < 32; k++) o += su[g * 32 + k] * W2[k * 4 + j];
        out[(size_t)N_NODES * 6 + g * 4 + j] = o;
    }
}

extern "C" void kernel_launch(void* const* d_in, const int* in_sizes, int n_in,
                              void* d_out, int out_size) {
    (void)in_sizes; (void)n_in; (void)out_size;
    const float* x     = (const float*)d_in[0];
    const int*   ei    = (const int*)d_in[1];
    const float* eattr = (const float*)d_in[2];
    const int*   batch = (const int*)d_in[3];
    const float* casep = (const float*)d_in[4];
    const float* bcp   = (const float*)d_in[5];
    const float* encW1 = (const float*)d_in[6];  const float* encb1 = (const float*)d_in[7];
    const float* encW2 = (const float*)d_in[8];  const float* encb2 = (const float*)d_in[9];
    const float* encg  = (const float*)d_in[10]; const float* encbe = (const float*)d_in[11];
    const float* eW1   = (const float*)d_in[12]; const float* eb1   = (const float*)d_in[13];
    const float* eW2   = (const float*)d_in[14]; const float* eb2   = (const float*)d_in[15];
    const float* eg    = (const float*)d_in[16]; const float* ebe   = (const float*)d_in[17];
    const float* nW1   = (const float*)d_in[18]; const float* nb1   = (const float*)d_in[19];
    const float* nW2   = (const float*)d_in[20]; const float* nb2   = (const float*)d_in[21];
    const float* ngm   = (const float*)d_in[22]; const float* nbe   = (const float*)d_in[23];
    const float* dlW1  = (const float*)d_in[24]; const float* dlb1  = (const float*)d_in[25];
    const float* dlW2  = (const float*)d_in[26]; const float* dlb2  = (const float*)d_in[27];
    const float* dgW1  = (const float*)d_in[28]; const float* dgb1  = (const float*)d_in[29];
    const float* dgW2  = (const float*)d_in[30]; const float* dgb2  = (const float*)d_in[31];
    float* out = (float*)d_out;

    size_t preSmem  = (size_t)(8192 + 8 * (8 * 68)) * sizeof(float);            // 50176 B
    size_t edgeSmem = (size_t)(4672 + 8 * 1280) * sizeof(float);                // 59648 B
    size_t updSmem  = (size_t)(12544 + 8 * (4 * 132 + 4 * 68)) * sizeof(float); // 75776 B
    cudaFuncSetAttribute(k_node_pre, cudaFuncAttributeMaxDynamicSharedMemorySize, (int)preSmem);
    cudaFuncSetAttribute(k_edge, cudaFuncAttributeMaxDynamicSharedMemorySize, (int)edgeSmem);
    cudaFuncSetAttribute(k_node_upd, cudaFuncAttributeMaxDynamicSharedMemorySize, (int)updSmem);

    k_encoder<<<(N_NODES + 7) / 8, 256>>>(x, batch, casep, bcp, encW1, encb1, encW2, encb2, encg, encbe);
    for (int l = 0; l < NL; l++) {
        const float* eW1l = eW1 + (size_t)l * 133 * 64;
        k_node_pre<<<592, 256, preSmem>>>(eW1l);
        k_edge<<<444, 256, edgeSmem>>>(ei, eattr,
                              eW1l + 128 * 64, eb1 + l * 64,
                              eW2 + (size_t)l * 4096, eb2 + l * 64,
                              eg + l * 64, ebe + l * 64);
        k_node_upd<<<444, 256, updSmem>>>(nW1 + (size_t)l * 8192, nb1 + l * 64,
                                          nW2 + (size_t)l * 4096, nb2 + l * 64,
                                          ngm + l * 64, nbe + l * 64);
    }
    k_zero_pool<<<1, 256>>>();
    k_decoder_local<<<(N_NODES + 7) / 8, 256>>>(dlW1, dlb1, dlW2, dlb2, batch, out);
    k_global<<<1, 128>>>(batch, dgW1, dgb1, dgW2, dgb2, out);
}

// round 4
// speedup vs baseline: 1.3367x; 1.3367x over previous
#include <cuda_runtime.h>

#define DINL __device__ __forceinline__

constexpr int N_NODES = 50000;
constexpr int N_EDGES = 1600000;
constexpr int NL = 5;
constexpr int NG = 4;
constexpr float EPS = 1e-5f;

__device__ float g_h  [N_NODES * 64];
__device__ float g_hd [N_NODES * 64];
__device__ float g_hs [N_NODES * 64];
__device__ float g_agg[N_NODES * 64];
__device__ float g_pool[NG * 64];

typedef unsigned long long u64;

DINL u64 pk2(float x, float y) { u64 r; asm("mov.b64 %0,{%1,%2};" : "=l"(r) : "f"(x), "f"(y)); return r; }
DINL u64 dup2(float x) { return pk2(x, x); }
DINL float2 upk(u64 v) { float2 r; asm("mov.b64 {%0,%1},%2;" : "=f"(r.x), "=f"(r.y) : "l"(v)); return r; }
DINL u64 ffma2(u64 a, u64 b, u64 c) {
    u64 d; asm("fma.rn.f32x2 %0,%1,%2,%3;" : "=l"(d) : "l"(a), "l"(b), "l"(c)); return d;
}
DINL u64 add2(u64 a, u64 b) {
    u64 d; asm("add.rn.f32x2 %0,%1,%2;" : "=l"(d) : "l"(a), "l"(b)); return d;
}
DINL void red2(float* p, float x, float y) {
    asm volatile("red.global.add.v2.f32 [%0], {%1,%2};" :: "l"(p), "f"(x), "f"(y) : "memory");
}
DINL float silu(float x) { return __fdividef(x, 1.f + __expf(-x)); }

// ============================ encoder ============================
__global__ void __launch_bounds__(256) k_encoder(
    const float* __restrict__ x, const int* __restrict__ batch,
    const float* __restrict__ casep, const float* __restrict__ bcp,
    const float* __restrict__ W1, const float* __restrict__ b1,
    const float* __restrict__ W2, const float* __restrict__ b2,
    const float* __restrict__ gam, const float* __restrict__ bet)
{
    __shared__ float sW1[16 * 64], sW2[64 * 64], sb1[64], sb2[64], sg[64], sbe[64];
    __shared__ float sH[8][64];
    int tid = threadIdx.x;
    for (int i = tid; i < 16 * 64; i += 256) sW1[i] = W1[i];
    for (int i = tid; i < 64 * 64; i += 256) sW2[i] = W2[i];
    if (tid < 64) { sb1[tid] = b1[tid]; sb2[tid] = b2[tid]; sg[tid] = gam[tid]; sbe[tid] = bet[tid]; }
    __syncthreads();
    int w = tid >> 5, ld = tid & 31, c0 = 2 * ld;
    int n = blockIdx.x * 8 + w;
    if (n >= N_NODES) return;
    float in[16];
#pragma unroll
    for (int k = 0; k < 8; k++) in[k] = __ldg(&x[n * 8 + k]);
    int g = __ldg(&batch[n]);
#pragma unroll
    for (int k = 0; k < 4; k++) { in[8 + k] = __ldg(&casep[g * 4 + k]); in[12 + k] = __ldg(&bcp[g * 4 + k]); }
    const u64* W1u = (const u64*)sW1;
    u64 acc = ((const u64*)sb1)[ld];
#pragma unroll
    for (int k = 0; k < 16; k++) acc = ffma2(dup2(in[k]), W1u[k * 32 + ld], acc);
    float2 a = upk(acc);
    a.x = silu(a.x); a.y = silu(a.y);
    sH[w][c0] = a.x; sH[w][c0 + 1] = a.y;
    __syncwarp();
    const u64* W2u = (const u64*)sW2;
    u64 acc2 = ((const u64*)sb2)[ld];
#pragma unroll 8
    for (int k = 0; k < 64; k++) acc2 = ffma2(dup2(sH[w][k]), W2u[k * 32 + ld], acc2);
    float2 v = upk(acc2);
    float s = v.x + v.y, q = v.x * v.x + v.y * v.y;
#pragma unroll
    for (int o = 16; o; o >>= 1) { s += __shfl_xor_sync(~0u, s, o); q += __shfl_xor_sync(~0u, q, o); }
    float m = s * (1.f / 64.f), var = q * (1.f / 64.f) - m * m, rs = rsqrtf(var + EPS);
    float2 out;
    out.x = (v.x - m) * rs * sg[c0] + sbe[c0];
    out.y = (v.y - m) * rs * sg[c0 + 1] + sbe[c0 + 1];
    *(float2*)(g_h + (size_t)n * 64 + c0) = out;
}

// ============================ node pre: Hd/Hs, 8 nodes/warp ============================
__global__ void __launch_bounds__(256) k_node_pre(const float* __restrict__ eW1l)
{
    extern __shared__ float ps[];
    float* sWA = ps;
    float* sWB = ps + 4096;
    float* sInAll = ps + 8192;
    int tid = threadIdx.x;
    for (int i = tid; i < 4096; i += 256) { sWA[i] = eW1l[i]; sWB[i] = eW1l[4096 + i]; }
    __syncthreads();
    int w = tid >> 5, ld = tid & 31;
    int nb = ld >> 3, cb = ld & 7;
    float* sIn = sInAll + w * (8 * 68);
    const ulonglong2* WAu = (const ulonglong2*)sWA;
    const ulonglong2* WBu = (const ulonglong2*)sWB;
    int gw = (blockIdx.x * 256 + tid) >> 5;
    int nw = (gridDim.x * 256) >> 5;
    for (int grp = gw; grp < N_NODES / 8; grp += nw) {
        int n0 = grp * 8;
        __syncwarp();
#pragma unroll
        for (int r = 0; r < 4; r++) {
            int t = r * 32 + ld;
            int n = t >> 4, c4 = (t & 15) * 4;
            float4 v = *(const float4*)(g_h + (size_t)(n0 + n) * 64 + c4);
            *(float4*)&sIn[n * 68 + c4] = v;
        }
        __syncwarp();
        u64 aA[2][4], aB[2][4];
#pragma unroll
        for (int i = 0; i < 2; i++)
#pragma unroll
            for (int j = 0; j < 4; j++) { aA[i][j] = 0ull; aB[i][j] = 0ull; }
#pragma unroll 4
        for (int k = 0; k < 64; k++) {
            u64 d0 = dup2(sIn[(nb * 2 + 0) * 68 + k]);
            u64 d1 = dup2(sIn[(nb * 2 + 1) * 68 + k]);
            ulonglong2 A0 = WAu[k * 16 + cb * 2], A1 = WAu[k * 16 + cb * 2 + 1];
            ulonglong2 B0 = WBu[k * 16 + cb * 2], B1 = WBu[k * 16 + cb * 2 + 1];
            aA[0][0] = ffma2(d0, A0.x, aA[0][0]); aA[0][1] = ffma2(d0, A0.y, aA[0][1]);
            aA[0][2] = ffma2(d0, A1.x, aA[0][2]); aA[0][3] = ffma2(d0, A1.y, aA[0][3]);
            aA[1][0] = ffma2(d1, A0.x, aA[1][0]); aA[1][1] = ffma2(d1, A0.y, aA[1][1]);
            aA[1][2] = ffma2(d1, A1.x, aA[1][2]); aA[1][3] = ffma2(d1, A1.y, aA[1][3]);
            aB[0][0] = ffma2(d0, B0.x, aB[0][0]); aB[0][1] = ffma2(d0, B0.y, aB[0][1]);
            aB[0][2] = ffma2(d0, B1.x, aB[0][2]); aB[0][3] = ffma2(d0, B1.y, aB[0][3]);
            aB[1][0] = ffma2(d1, B0.x, aB[1][0]); aB[1][1] = ffma2(d1, B0.y, aB[1][1]);
            aB[1][2] = ffma2(d1, B1.x, aB[1][2]); aB[1][3] = ffma2(d1, B1.y, aB[1][3]);
        }
#pragma unroll
        for (int i = 0; i < 2; i++) {
            int n = n0 + nb * 2 + i;
            ulonglong2 t;
            t.x = aA[i][0]; t.y = aA[i][1];
            *(ulonglong2*)(g_hd + (size_t)n * 64 + cb * 8) = t;
            t.x = aA[i][2]; t.y = aA[i][3];
            *(ulonglong2*)(g_hd + (size_t)n * 64 + cb * 8 + 4) = t;
            t.x = aB[i][0]; t.y = aB[i][1];
            *(ulonglong2*)(g_hs + (size_t)n * 64 + cb * 8) = t;
            t.x = aB[i][2]; t.y = aB[i][3];
            *(ulonglong2*)(g_hs + (size_t)n * 64 + cb * 8 + 4) = t;
            *(float4*)(g_agg + (size_t)n * 64 + cb * 8)     = make_float4(0.f, 0.f, 0.f, 0.f);
            *(float4*)(g_agg + (size_t)n * 64 + cb * 8 + 4) = make_float4(0.f, 0.f, 0.f, 0.f);
        }
    }
}

// ============================ edge kernel: 32 edges/warp, thread = 8 edges x 8 cols ============================
// dyn smem layout (floats):
//   sW2s [0,4608)      W2 rows stride 72: cols 0-31 at +0, cols 32-63 at +36 (bank-conflict-free)
//   sW1c [4608,4928)   5x64
//   sb1  [4928,4992)   sb2 [4992,5056)  sg [5056,5120)  sbe [5120,5184)
//   per-warp [5184 + w*2336): sM [64 k][36] transposed m, then sD int[32]
__global__ void __launch_bounds__(256, 2) k_edge(
    const int* __restrict__ ei, const float* __restrict__ eattr,
    const float* __restrict__ W1c, const float* __restrict__ b1,
    const float* __restrict__ W2, const float* __restrict__ b2,
    const float* __restrict__ gam, const float* __restrict__ bet)
{
    extern __shared__ float es[];
    float* sW2s = es;
    float* sW1c = es + 4608;
    float* sb1  = es + 4928;
    float* sb2  = es + 4992;
    float* sg   = es + 5056;
    float* sbe  = es + 5120;
    float* sPer = es + 5184;
    int tid = threadIdx.x;
    for (int i = tid; i < 4096; i += 256) {
        int k = i >> 6, c = i & 63;
        sW2s[k * 72 + (c < 32 ? c : c + 4)] = W2[i];
    }
    for (int i = tid; i < 320; i += 256) sW1c[i] = W1c[i];
    if (tid < 64) { sb1[tid] = b1[tid]; sb2[tid] = b2[tid]; sg[tid] = gam[tid]; sbe[tid] = bet[tid]; }
    __syncthreads();
    int w = tid >> 5, ld = tid & 31;
    int pe = ld >> 1, half = ld & 1;          // phase-1 mapping: 16 edges x 2 halves
    int eb = ld >> 3, cb = ld & 7;            // phase-2 mapping: 4 edge-blocks x 8 col-blocks
    float* sM = sPer + w * 2336;
    int* sD = (int*)(sM + 2304);
    int wOff = (cb < 4) ? cb * 8 : 36 + (cb - 4) * 8;
    const ulonglong2* W1cu = (const ulonglong2*)sW1c;
    const ulonglong2* b1u  = (const ulonglong2*)sb1;
    const u64* b2u = (const u64*)sb2;
    const float4* gv4  = (const float4*)sg;
    const float4* bev4 = (const float4*)sbe;
    int gw = (blockIdx.x * 256 + tid) >> 5;
    int nw = (gridDim.x * 256) >> 5;
    for (int grp = gw; grp < N_EDGES / 32; grp += nw) {
        int e0 = grp * 32;
        __syncwarp();   // WAR: previous iteration's sM reads done
        // ---- phase 1: m = silu(Hd[dst]+Hs[src]+ea@W1c+b1), store transposed ----
#pragma unroll
        for (int sub = 0; sub < 2; sub++) {
            int e = e0 + sub * 16 + pe;
            int sidx = __ldg(&ei[e]);
            int didx = __ldg(&ei[N_EDGES + e]);
            if (half == 0) sD[sub * 16 + pe] = didx;
            u64 ead[5];
#pragma unroll
            for (int r = 0; r < 5; r++) ead[r] = dup2(__ldg(&eattr[(size_t)e * 5 + r]));
            const ulonglong2* hdp = (const ulonglong2*)(g_hd + (size_t)didx * 64 + half * 32);
            const ulonglong2* hsp = (const ulonglong2*)(g_hs + (size_t)sidx * 64 + half * 32);
#pragma unroll
            for (int j = 0; j < 8; j++) {
                ulonglong2 hdj = hdp[j];
                ulonglong2 hsj = hsp[j];
                ulonglong2 bj  = b1u[half * 8 + j];
                u64 a0 = add2(add2(hdj.x, hsj.x), bj.x);
                u64 a1 = add2(add2(hdj.y, hsj.y), bj.y);
#pragma unroll
                for (int r = 0; r < 5; r++) {
                    ulonglong2 wv = W1cu[r * 16 + half * 8 + j];
                    a0 = ffma2(ead[r], wv.x, a0);
                    a1 = ffma2(ead[r], wv.y, a1);
                }
                float2 v0 = upk(a0), v1 = upk(a1);
                v0.x = silu(v0.x); v0.y = silu(v0.y);
                v1.x = silu(v1.x); v1.y = silu(v1.y);
                int c = half * 32 + 4 * j;
                int col = sub * 16 + pe;
                sM[(c + 0) * 36 + col] = v0.x;
                sM[(c + 1) * 36 + col] = v0.y;
                sM[(c + 2) * 36 + col] = v1.x;
                sM[(c + 3) * 36 + col] = v1.y;
            }
        }
        __syncwarp();
        // ---- phase 2: [32 e x 64 c] = m[32 x 64k] @ W2, thread = 8e x 8c ----
        u64 acc[8][4];
#pragma unroll
        for (int i = 0; i < 8; i++)
#pragma unroll
            for (int j = 0; j < 4; j++) acc[i][j] = b2u[cb * 4 + j];
#pragma unroll 4
        for (int k = 0; k < 64; k++) {
            const float4* mp = (const float4*)&sM[k * 36 + eb * 8];
            float4 m0 = mp[0], m1 = mp[1];
            ulonglong2 wA = *(const ulonglong2*)&sW2s[k * 72 + wOff];
            ulonglong2 wB = *(const ulonglong2*)&sW2s[k * 72 + wOff + 4];
            u64 mm[8];
            mm[0] = dup2(m0.x); mm[1] = dup2(m0.y); mm[2] = dup2(m0.z); mm[3] = dup2(m0.w);
            mm[4] = dup2(m1.x); mm[5] = dup2(m1.y); mm[6] = dup2(m1.z); mm[7] = dup2(m1.w);
#pragma unroll
            for (int i = 0; i < 8; i++) {
                acc[i][0] = ffma2(mm[i], wA.x, acc[i][0]);
                acc[i][1] = ffma2(mm[i], wA.y, acc[i][1]);
                acc[i][2] = ffma2(mm[i], wB.x, acc[i][2]);
                acc[i][3] = ffma2(mm[i], wB.y, acc[i][3]);
            }
        }
        // ---- LN per edge (reduce over cb lanes within 8-lane groups) + scatter ----
        float s[8], q[8];
#pragma unroll
        for (int i = 0; i < 8; i++) {
            float2 v0 = upk(acc[i][0]), v1 = upk(acc[i][1]), v2 = upk(acc[i][2]), v3 = upk(acc[i][3]);
            s[i] = v0.x + v0.y + v1.x + v1.y + v2.x + v2.y + v3.x + v3.y;
            q[i] = v0.x * v0.x + v0.y * v0.y + v1.x * v1.x + v1.y * v1.y
                 + v2.x * v2.x + v2.y * v2.y + v3.x * v3.x + v3.y * v3.y;
        }
#pragma unroll
        for (int o = 4; o; o >>= 1) {
#pragma unroll
            for (int i = 0; i < 8; i++) {
                s[i] += __shfl_xor_sync(~0u, s[i], o);
                q[i] += __shfl_xor_sync(~0u, q[i], o);
            }
        }
        float4 gA = gv4[cb * 2], gB = gv4[cb * 2 + 1];
        float4 beA = bev4[cb * 2], beB = bev4[cb * 2 + 1];
#pragma unroll
        for (int i = 0; i < 8; i++) {
            int dI = sD[eb * 8 + i];
            float mn = s[i] * (1.f / 64.f);
            float rs = rsqrtf(q[i] * (1.f / 64.f) - mn * mn + EPS);
            float2 v0 = upk(acc[i][0]), v1 = upk(acc[i][1]), v2 = upk(acc[i][2]), v3 = upk(acc[i][3]);
            float* base = g_agg + (size_t)dI * 64 + cb * 8;
            red2(base + 0, (v0.x - mn) * rs * gA.x + beA.x, (v0.y - mn) * rs * gA.y + beA.y);
            red2(base + 2, (v1.x - mn) * rs * gA.z + beA.z, (v1.y - mn) * rs * gA.w + beA.w);
            red2(base + 4, (v2.x - mn) * rs * gB.x + beB.x, (v2.y - mn) * rs * gB.y + beB.y);
            red2(base + 6, (v3.x - mn) * rs * gB.z + beB.z, (v3.y - mn) * rs * gB.w + beB.w);
        }
    }
}

// ============================ node update: 8 nodes/warp, thread = 2n x 8c ============================
// dyn smem: sW1[8192] sW2[4096] biases[256] | per-warp sIn[8*132] sMid[8*70]
__global__ void __launch_bounds__(256) k_node_upd(
    const float* __restrict__ W1, const float* __restrict__ b1,
    const float* __restrict__ W2, const float* __restrict__ b2,
    const float* __restrict__ gam, const float* __restrict__ bet)
{
    extern __shared__ float us[];
    float* sW1 = us;
    float* sW2 = us + 8192;
    float* sb1 = us + 12288;
    float* sb2 = us + 12352;
    float* sg  = us + 12416;
    float* sbe = us + 12480;
    float* sPer = us + 12544;
    int tid = threadIdx.x;
    for (int i = tid; i < 8192; i += 256) sW1[i] = W1[i];
    for (int i = tid; i < 4096; i += 256) sW2[i] = W2[i];
    if (tid < 64) { sb1[tid] = b1[tid]; sb2[tid] = b2[tid]; sg[tid] = gam[tid]; sbe[tid] = bet[tid]; }
    __syncthreads();
    int w = tid >> 5, ld = tid & 31;
    int nb = ld >> 3, cb = ld & 7;
    float* sIn  = sPer + w * (8 * 132 + 8 * 70);
    float* sMid = sIn + 8 * 132;
    const ulonglong2* W1u = (const ulonglong2*)sW1;
    const ulonglong2* W2u = (const ulonglong2*)sW2;
    const u64* b1u = (const u64*)sb1;
    const u64* b2u = (const u64*)sb2;
    const float4* gv4  = (const float4*)sg;
    const float4* bev4 = (const float4*)sbe;
    int gw = (blockIdx.x * 256 + tid) >> 5;
    int nw = (gridDim.x * 256) >> 5;
    for (int grp = gw; grp < N_NODES / 8; grp += nw) {
        int n0 = grp * 8;
        __syncwarp();
#pragma unroll
        for (int r = 0; r < 8; r++) {
            int c4 = ld * 4;
            float4 v;
            if (c4 < 64) v = *(const float4*)(g_h + (size_t)(n0 + r) * 64 + c4);
            else         v = *(const float4*)(g_agg + (size_t)(n0 + r) * 64 + (c4 - 64));
            *(float4*)&sIn[r * 132 + c4] = v;
        }
        __syncwarp();
        // GEMM1: [8 x 128] @ [128 x 64], thread = 2 nodes x 8 cols
        u64 a1[2][4];
#pragma unroll
        for (int i = 0; i < 2; i++)
#pragma unroll
            for (int j = 0; j < 4; j++) a1[i][j] = b1u[cb * 4 + j];
#pragma unroll 4
        for (int k = 0; k < 128; k++) {
            u64 d0 = dup2(sIn[(nb * 2 + 0) * 132 + k]);
            u64 d1 = dup2(sIn[(nb * 2 + 1) * 132 + k]);
            ulonglong2 w0 = W1u[k * 16 + cb * 2], w1 = W1u[k * 16 + cb * 2 + 1];
            a1[0][0] = ffma2(d0, w0.x, a1[0][0]); a1[0][1] = ffma2(d0, w0.y, a1[0][1]);
            a1[0][2] = ffma2(d0, w1.x, a1[0][2]); a1[0][3] = ffma2(d0, w1.y, a1[0][3]);
            a1[1][0] = ffma2(d1, w0.x, a1[1][0]); a1[1][1] = ffma2(d1, w0.y, a1[1][1]);
            a1[1][2] = ffma2(d1, w1.x, a1[1][2]); a1[1][3] = ffma2(d1, w1.y, a1[1][3]);
        }
#pragma unroll
        for (int i = 0; i < 2; i++) {
            int n = nb * 2 + i;
#pragma unroll
            for (int j = 0; j < 4; j++) {
                float2 v = upk(a1[i][j]);
                v.x = silu(v.x); v.y = silu(v.y);
                *(float2*)&sMid[n * 70 + cb * 8 + 2 * j] = v;
            }
        }
        __syncwarp();
        // GEMM2: [8 x 64] @ [64 x 64]
        u64 a2[2][4];
#pragma unroll
        for (int i = 0; i < 2; i++)
#pragma unroll
            for (int j = 0; j < 4; j++) a2[i][j] = b2u[cb * 4 + j];
#pragma unroll 4
        for (int k = 0; k < 64; k++) {
            u64 d0 = dup2(sMid[(nb * 2 + 0) * 70 + k]);
            u64 d1 = dup2(sMid[(nb * 2 + 1) * 70 + k]);
            ulonglong2 w0 = W2u[k * 16 + cb * 2], w1 = W2u[k * 16 + cb * 2 + 1];
            a2[0][0] = ffma2(d0, w0.x, a2[0][0]); a2[0][1] = ffma2(d0, w0.y, a2[0][1]);
            a2[0][2] = ffma2(d0, w1.x, a2[0][2]); a2[0][3] = ffma2(d0, w1.y, a2[0][3]);
            a2[1][0] = ffma2(d1, w0.x, a2[1][0]); a2[1][1] = ffma2(d1, w0.y, a2[1][1]);
            a2[1][2] = ffma2(d1, w1.x, a2[1][2]); a2[1][3] = ffma2(d1, w1.y, a2[1][3]);
        }
        // LN + residual
        float4 gA = gv4[cb * 2], gB = gv4[cb * 2 + 1];
        float4 beA = bev4[cb * 2], beB = bev4[cb * 2 + 1];
#pragma unroll
        for (int i = 0; i < 2; i++) {
            float2 v0 = upk(a2[i][0]), v1 = upk(a2[i][1]), v2 = upk(a2[i][2]), v3 = upk(a2[i][3]);
            float s = v0.x + v0.y + v1.x + v1.y + v2.x + v2.y + v3.x + v3.y;
            float q = v0.x * v0.x + v0.y * v0.y + v1.x * v1.x + v1.y * v1.y
                    + v2.x * v2.x + v2.y * v2.y + v3.x * v3.x + v3.y * v3.y;
#pragma unroll
            for (int o = 4; o; o >>= 1) { s += __shfl_xor_sync(~0u, s, o); q += __shfl_xor_sync(~0u, q, o); }
            float mn = s * (1.f / 64.f);
            float rs = rsqrtf(q * (1.f / 64.f) - mn * mn + EPS);
            int n = nb * 2 + i;
            float4 h0 = *(const float4*)&sIn[n * 132 + cb * 8];
            float4 h1 = *(const float4*)&sIn[n * 132 + cb * 8 + 4];
            float4 o0, o1;
            o0.x = h0.x + (v0.x - mn) * rs * gA.x + beA.x;
            o0.y = h0.y + (v0.y - mn) * rs * gA.y + beA.y;
            o0.z = h0.z + (v1.x - mn) * rs * gA.z + beA.z;
            o0.w = h0.w + (v1.y - mn) * rs * gA.w + beA.w;
            o1.x = h1.x + (v2.x - mn) * rs * gB.x + beB.x;
            o1.y = h1.y + (v2.y - mn) * rs * gB.y + beB.y;
            o1.z = h1.z + (v3.x - mn) * rs * gB.z + beB.z;
            o1.w = h1.w + (v3.y - mn) * rs * gB.w + beB.w;
            *(float4*)(g_h + (size_t)(n0 + n) * 64 + cb * 8)     = o0;
            *(float4*)(g_h + (size_t)(n0 + n) * 64 + cb * 8 + 4) = o1;
        }
    }
}

__global__ void k_zero_pool() { int t = threadIdx.x; if (t < NG * 64) g_pool[t] = 0.f; }

// ============================ local decoder + pooling ============================
__global__ void __launch_bounds__(256) k_decoder_local(
    const float* __restrict__ W1, const float* __restrict__ b1,
    const float* __restrict__ W2, const float* __restrict__ b2,
    const int* __restrict__ batch, float* __restrict__ out)
{
    __shared__ float sW1[4096], sW2[64 * 6], sb1[64], sb2_[8];
    __shared__ float sH[8][64], sU[8][64];
    int tid = threadIdx.x;
    for (int i = tid; i < 4096; i += 256) sW1[i] = W1[i];
    for (int i = tid; i < 384; i += 256) sW2[i] = W2[i];
    if (tid < 64) sb1[tid] = b1[tid];
    if (tid < 6) sb2_[tid] = b2[tid];
    __syncthreads();
    int w = tid >> 5, ld = tid & 31, c0 = 2 * ld;
    int n = blockIdx.x * 8 + w;
    if (n >= N_NODES) return;
    float2 hv = *(const float2*)(g_h + (size_t)n * 64 + c0);
    sH[w][c0] = hv.x; sH[w][c0 + 1] = hv.y;
    __syncwarp();
    const u64* W1u = (const u64*)sW1;
    u64 acc = ((const u64*)sb1)[ld];
#pragma unroll 8
    for (int k = 0; k < 64; k++) acc = ffma2(dup2(sH[w][k]), W1u[k * 32 + ld], acc);
    float2 u = upk(acc); u.x = silu(u.x); u.y = silu(u.y);
    sU[w][c0] = u.x; sU[w][c0 + 1] = u.y;
    __syncwarp();
    if (ld < 6) {
        float o = sb2_[ld];
#pragma unroll
        for (int k = 0; k < 64; k++) o += sU[w][k] * sW2[k * 6 + ld];
        out[(size_t)n * 6 + ld] = o;
    }
    int g = __ldg(&batch[n]);
    red2(g_pool + g * 64 + c0, hv.x, hv.y);
}

// ============================ global decoder ============================
__global__ void k_global(const int* __restrict__ batch,
    const float* __restrict__ W1, const float* __restrict__ b1,
    const float* __restrict__ W2, const float* __restrict__ b2,
    float* __restrict__ out)
{
    __shared__ float sp[NG * 64];
    __shared__ float su[NG * 32];
    __shared__ int bnd[NG + 1];
    int t = threadIdx.x;
    if (t <= NG) {
        int lo = 0, hi = N_NODES;
        while (lo < hi) { int mid = (lo + hi) >> 1; if (batch[mid] < t) lo = mid + 1; else hi = mid; }
        bnd[t] = lo;
    }
    __syncthreads();
    for (int i = t; i < NG * 64; i += 128) {
        int g = i >> 6;
        float cnt = (float)(bnd[g + 1] - bnd[g]);
        sp[i] = g_pool[i] / fmaxf(cnt, 1.f);
    }
    __syncthreads();
    {
        int g = t >> 5, j = t & 31;
        float a = b1[j];
#pragma unroll
        for (int k = 0; k < 64; k++) a += sp[g * 64 + k] * W1[k * 32 + j];
        su[g * 32 + j] = silu(a);
    }
    __syncthreads();
    if (t < NG * 4) {
        int g = t >> 2, j = t & 3;
        float o = b2[j];
#pragma unroll
        for (int k = 0; k < 32; k++) o += su[g * 32 + k] * W2[k * 4 + j];
        out[(size_t)N_NODES * 6 + g * 4 + j] = o;
    }
}

extern "C" void kernel_launch(void* const* d_in, const int* in_sizes, int n_in,
                              void* d_out, int out_size) {
    (void)in_sizes; (void)n_in; (void)out_size;
    const float* x     = (const float*)d_in[0];
    const int*   ei    = (const int*)d_in[1];
    const float* eattr = (const float*)d_in[2];
    const int*   batch = (const int*)d_in[3];
    const float* casep = (const float*)d_in[4];
    const float* bcp   = (const float*)d_in[5];
    const float* encW1 = (const float*)d_in[6];  const float* encb1 = (const float*)d_in[7];
    const float* encW2 = (const float*)d_in[8];  const float* encb2 = (const float*)d_in[9];
    const float* encg  = (const float*)d_in[10]; const float* encbe = (const float*)d_in[11];
    const float* eW1   = (const float*)d_in[12]; const float* eb1   = (const float*)d_in[13];
    const float* eW2   = (const float*)d_in[14]; const float* eb2   = (const float*)d_in[15];
    const float* eg    = (const float*)d_in[16]; const float* ebe   = (const float*)d_in[17];
    const float* nW1   = (const float*)d_in[18]; const float* nb1   = (const float*)d_in[19];
    const float* nW2   = (const float*)d_in[20]; const float* nb2   = (const float*)d_in[21];
    const float* ngm   = (const float*)d_in[22]; const float* nbe   = (const float*)d_in[23];
    const float* dlW1  = (const float*)d_in[24]; const float* dlb1  = (const float*)d_in[25];
    const float* dlW2  = (const float*)d_in[26]; const float* dlb2  = (const float*)d_in[27];
    const float* dgW1  = (const float*)d_in[28]; const float* dgb1  = (const float*)d_in[29];
    const float* dgW2  = (const float*)d_in[30]; const float* dgb2  = (const float*)d_in[31];
    float* out = (float*)d_out;

    size_t preSmem  = (size_t)(8192 + 8 * (8 * 68)) * sizeof(float);            // 50176 B
    size_t edgeSmem = (size_t)(5184 + 8 * 2336) * sizeof(float);                // 95488 B
    size_t updSmem  = (size_t)(12544 + 8 * (8 * 132 + 8 * 70)) * sizeof(float); // 101888 B
    cudaFuncSetAttribute(k_node_pre, cudaFuncAttributeMaxDynamicSharedMemorySize, (int)preSmem);
    cudaFuncSetAttribute(k_edge, cudaFuncAttributeMaxDynamicSharedMemorySize, (int)edgeSmem);
    cudaFuncSetAttribute(k_node_upd, cudaFuncAttributeMaxDynamicSharedMemorySize, (int)updSmem);

    k_encoder<<<(N_NODES + 7) / 8, 256>>>(x, batch, casep, bcp, encW1, encb1, encW2, encb2, encg, encbe);
    for (int l = 0; l < NL; l++) {
        const float* eW1l = eW1 + (size_t)l * 133 * 64;
        k_node_pre<<<592, 256, preSmem>>>(eW1l);
        k_edge<<<296, 256, edgeSmem>>>(ei, eattr,
                              eW1l + 128 * 64, eb1 + l * 64,
                              eW2 + (size_t)l * 4096, eb2 + l * 64,
                              eg + l * 64, ebe + l * 64);
        k_node_upd<<<296, 256, updSmem>>>(nW1 + (size_t)l * 8192, nb1 + l * 64,
                                          nW2 + (size_t)l * 4096, nb2 + l * 64,
                                          ngm + l * 64, nbe + l * 64);
    }
    k_zero_pool<<<1, 256>>>();
    k_decoder_local<<<(N_NODES + 7) / 8, 256>>>(dlW1, dlb1, dlW2, dlb2, batch, out);
    k_global<<<1, 128>>>(batch, dgW1, dgb1, dgW2, dgb2, out);
}